// round 5
// baseline (speedup 1.0000x reference)
#include <cuda_runtime.h>
#include <math_constants.h>

// Jagged log-softmax, round 5: two-kernel split.
//  k1: block-per-segment lse (reads 64MB, leaves logits in L2)
//  k2: flat balanced write kernel, no barriers: out[i] = x[i] - lse[seg(i)]
//      (logits re-read hits L2; seg found via per-thread binary search +
//       monotone pointer; prefix_sum 32KB stays L1-resident)

#define T1 128              // k1 threads (4 warps -> cheap block reduce)
#define T2 256              // k2 threads
#define IT2 16              // float4s per thread in k2
#define CHUNK (T2 * IT2)    // 4096 float4s = 16384 elems per k2 block

__device__ float g_lse[1 << 16];   // per-segment log-sum-exp

__device__ __forceinline__ float warp_sum(float v) {
    #pragma unroll
    for (int o = 16; o > 0; o >>= 1)
        v += __shfl_xor_sync(0xFFFFFFFFu, v, o);
    return v;
}

// ---------------- k1: per-segment lse ----------------
__global__ void __launch_bounds__(T1)
lse_kernel(const float* __restrict__ logits,
           const int* __restrict__ prefix_sum) {
    __shared__ float sm[T1 / 32];

    const int seg   = blockIdx.x;
    const int start = (seg == 0) ? 0 : __ldg(&prefix_sum[seg - 1]);
    const int end   = __ldg(&prefix_sum[seg]);
    if (start >= end) return;     // empty segment: lse never read

    const int tid  = threadIdx.x;
    const int lane = tid & 31;
    const int warp = tid >> 5;

    int astart = (start + 3) & ~3; if (astart > end) astart = end;
    int aend   = end & ~3;         if (aend < astart) aend = astart;

    const float4* __restrict__ logits4 = (const float4*)logits;

    float s = 0.0f;
    for (int i = start + tid; i < astart; i += T1)
        s += __expf(__ldg(&logits[i]));
    #pragma unroll 4
    for (int i = astart + tid * 4; i < aend; i += T1 * 4) {
        float4 v = __ldg(&logits4[i >> 2]);
        s += __expf(v.x) + __expf(v.y) + __expf(v.z) + __expf(v.w);
    }
    for (int i = aend + tid; i < end; i += T1)
        s += __expf(__ldg(&logits[i]));

    s = warp_sum(s);
    if (lane == 0) sm[warp] = s;
    __syncthreads();
    if (warp == 0) {
        float v = (lane < T1 / 32) ? sm[lane] : 0.0f;
        #pragma unroll
        for (int o = (T1 / 32) / 2; o > 0; o >>= 1)
            v += __shfl_xor_sync(0xFFFFFFFFu, v, o);
        if (lane == 0) g_lse[seg] = __logf(v);
    }
}

// ---------------- k2: flat write ----------------
__global__ void __launch_bounds__(T2)
write_kernel(const float* __restrict__ logits,
             const int* __restrict__ prefix_sum,
             float* __restrict__ out,
             int total4, int nseg) {
    const int tid   = threadIdx.x;
    const int base4 = blockIdx.x * CHUNK;

    int idx4 = base4 + tid;
    if (idx4 >= total4) return;

    // initial binary search: seg = first j with prefix_sum[j] > e0
    int e0 = idx4 * 4;
    int lo = 0, hi = nseg;
    while (lo < hi) {
        int mid = (lo + hi) >> 1;
        if (__ldg(&prefix_sum[mid]) <= e0) lo = mid + 1; else hi = mid;
    }
    int seg = lo;
    int pe  = __ldg(&prefix_sum[seg]);   // end of current segment

    const float4* __restrict__ logits4 = (const float4*)logits;
    float4*       __restrict__ out4    = (float4*)out;

    #pragma unroll 4
    for (int it = 0; it < IT2; it++) {
        int i4 = base4 + tid + it * T2;
        if (i4 >= total4) break;
        int e = i4 * 4;

        while (e >= pe) pe = __ldg(&prefix_sum[++seg]);   // monotone advance

        float4 v = __ldg(&logits4[i4]);
        float4 r;
        if (e + 4 <= pe) {                       // common case: one segment
            float L = g_lse[seg];
            r.x = v.x - L; r.y = v.y - L; r.z = v.z - L; r.w = v.w - L;
        } else {                                 // boundary splits the float4
            int s2 = seg, p2 = pe;
            float xs[4] = {v.x, v.y, v.z, v.w};
            float rs[4];
            #pragma unroll
            for (int k = 0; k < 4; k++) {
                while (e + k >= p2) p2 = __ldg(&prefix_sum[++s2]);
                rs[k] = xs[k] - g_lse[s2];
            }
            r.x = rs[0]; r.y = rs[1]; r.z = rs[2]; r.w = rs[3];
        }
        __stcs(&out4[i4], r);
    }
}

extern "C" void kernel_launch(void* const* d_in, const int* in_sizes, int n_in,
                              void* d_out, int out_size) {
    const float* logits     = (const float*)d_in[0];
    const int*   prefix_sum = (const int*)d_in[1];
    float*       out        = (float*)d_out;

    const int num_segs = in_sizes[1];
    const int total    = out_size;
    const int total4   = total >> 2;    // total is a multiple of 4
    const int grid2    = (total4 + CHUNK - 1) / CHUNK;

    lse_kernel<<<num_segs, T1>>>(logits, prefix_sum);
    write_kernel<<<grid2, T2>>>(logits, prefix_sum, out, total4, num_segs);
}